// round 7
// baseline (speedup 1.0000x reference)
#include <cuda_runtime.h>
#include <cuda_bf16.h>
#include <cstdint>

// RobustTripletLoss — N=4096, D=512, C=128, TOPK=12
// k_prep : X fp32 -> (Xhi, Xlo) bf16 split + row sq-norms
// k_gemm : HMMA (mma.sync bf16) symmetric Gram, 3-term hi/lo per chunk,
//          cp.async double-buffered (4 tiles/chunk) -> dist (64MB scratch)
// k_row  : per-row reduce, 512 thr (top-12, threefry gumbel, case logic)
// k_final: deterministic reduce -> out[0]=loss, out[1]=(float)correct

namespace {

constexpr int NROW = 4096;
constexpr int DIM  = 512;
constexpr int NCLS = 128;
constexpr int KTOP = 12;

__device__ __align__(16) float g_dist[(size_t)NROW * NROW];
__device__ __align__(16) float g_sq[NROW];
__device__ __align__(16) __nv_bfloat16 g_xhi[(size_t)NROW * DIM];
__device__ __align__(16) __nv_bfloat16 g_xlo[(size_t)NROW * DIM];
__device__ float g_rowloss[NROW];
__device__ int   g_flags[NROW];

// ---------------- threefry2x32-20 (exact JAX semantics) ----------------
__host__ __device__ inline uint2 tf2x32(unsigned k0, unsigned k1,
                                        unsigned x0, unsigned x1) {
    unsigned ks2 = k0 ^ k1 ^ 0x1BD11BDAu;
    x0 += k0; x1 += k1;
#define TF_R(r) { x0 += x1; x1 = (x1 << (r)) | (x1 >> (32 - (r))); x1 ^= x0; }
    TF_R(13) TF_R(15) TF_R(26) TF_R(6)
    x0 += k1;  x1 += ks2 + 1u;
    TF_R(17) TF_R(29) TF_R(16) TF_R(24)
    x0 += ks2; x1 += k0 + 2u;
    TF_R(13) TF_R(15) TF_R(26) TF_R(6)
    x0 += k0;  x1 += k1 + 3u;
    TF_R(17) TF_R(29) TF_R(16) TF_R(24)
    x0 += k1;  x1 += ks2 + 4u;
    TF_R(13) TF_R(15) TF_R(26) TF_R(6)
    x0 += ks2; x1 += k0 + 5u;
#undef TF_R
    uint2 r; r.x = x0; r.y = x1; return r;
}

__device__ __forceinline__ unsigned rbits32(unsigned k0, unsigned k1, unsigned m) {
    uint2 e = tf2x32(k0, k1, 0u, m);
    return e.x ^ e.y;
}

__device__ __forceinline__ float devInf() { return __int_as_float(0x7f800000); }

__device__ __forceinline__ uint32_t smem_to_u32(const void* p) {
    uint32_t a;
    asm("{ .reg .u64 t; cvta.to.shared.u64 t, %1; cvt.u32.u64 %0, t; }"
        : "=r"(a) : "l"(p));
    return a;
}

// ---------------- k_prep: bf16 hi/lo split + row norms ----------------
__global__ void __launch_bounds__(256) k_prep(const float* __restrict__ X) {
    int row  = blockIdx.x * 8 + (threadIdx.x >> 5);
    int lane = threadIdx.x & 31;
    const float4* p = (const float4*)(X + (size_t)row * DIM);
    float s = 0.f;
#pragma unroll
    for (int it = 0; it < 4; it++) {
        int f = lane + it * 32;
        float4 v = p[f];
        s = fmaf(v.x, v.x, fmaf(v.y, v.y, fmaf(v.z, v.z, fmaf(v.w, v.w, s))));
        __nv_bfloat16 h0 = __float2bfloat16(v.x);
        __nv_bfloat16 h1 = __float2bfloat16(v.y);
        __nv_bfloat16 h2 = __float2bfloat16(v.z);
        __nv_bfloat16 h3 = __float2bfloat16(v.w);
        __nv_bfloat16 l0 = __float2bfloat16(v.x - __bfloat162float(h0));
        __nv_bfloat16 l1 = __float2bfloat16(v.y - __bfloat162float(h1));
        __nv_bfloat16 l2 = __float2bfloat16(v.z - __bfloat162float(h2));
        __nv_bfloat16 l3 = __float2bfloat16(v.w - __bfloat162float(h3));
        size_t base = (size_t)row * DIM + (size_t)f * 4;
        *(__nv_bfloat162*)&g_xhi[base]     = __halves2bfloat162(h0, h1);
        *(__nv_bfloat162*)&g_xhi[base + 2] = __halves2bfloat162(h2, h3);
        *(__nv_bfloat162*)&g_xlo[base]     = __halves2bfloat162(l0, l1);
        *(__nv_bfloat162*)&g_xlo[base + 2] = __halves2bfloat162(l2, l3);
    }
#pragma unroll
    for (int o = 16; o > 0; o >>= 1) s += __shfl_xor_sync(0xffffffffu, s, o);
    if (lane == 0) g_sq[row] = s;
}

// ---------------- k_gemm: HMMA bf16x3 symmetric Gram ----------------
// smem: [0..512) sqn stage | [512..) 2 x 64KB chunk buffers
//       each chunk buffer = Ahi 16K | Alo 16K | Bhi 16K | Blo 16K
// Dt (float 128x129) reuses [512..66560) after compute.
constexpr int OFF_BUF  = 512;
constexpr int BUF_SZ   = 65536;
constexpr int T_AH = 0, T_AL = 16384, T_BH = 32768, T_BL = 49152;
constexpr int SMEM_DYN = 512 + 2 * BUF_SZ;   // 131584

// per tile: 128 rows x 64 bf16 (=128B rows), 16B group g swizzled by row: g^(row&7)
__device__ __forceinline__ void prefetch_chunk4(
    int bi, int bj, int kb, uint32_t sbuf, int tid)
{
#pragma unroll
    for (int it = 0; it < 4; it++) {
        int idx = tid + it * 256;
        int row = idx >> 3, g = idx & 7;
        unsigned sw = ((unsigned)(g ^ (row & 7))) << 4;
        size_t offA = (size_t)(bi * 128 + row) * DIM + kb * 64 + g * 8;
        size_t offB = (size_t)(bj * 128 + row) * DIM + kb * 64 + g * 8;
        uint32_t d = sbuf + row * 128 + sw;
        asm volatile("cp.async.cg.shared.global [%0], [%1], 16;"
                     :: "r"(d + T_AH), "l"((const void*)(g_xhi + offA)));
        asm volatile("cp.async.cg.shared.global [%0], [%1], 16;"
                     :: "r"(d + T_AL), "l"((const void*)(g_xlo + offA)));
        asm volatile("cp.async.cg.shared.global [%0], [%1], 16;"
                     :: "r"(d + T_BH), "l"((const void*)(g_xhi + offB)));
        asm volatile("cp.async.cg.shared.global [%0], [%1], 16;"
                     :: "r"(d + T_BL), "l"((const void*)(g_xlo + offB)));
    }
    asm volatile("cp.async.commit_group;" ::: "memory");
}

__device__ __forceinline__ void mma16816(float* c, const uint32_t* a,
                                         const uint32_t* b) {
    asm volatile(
        "mma.sync.aligned.m16n8k16.row.col.f32.bf16.bf16.f32 "
        "{%0,%1,%2,%3}, {%4,%5,%6,%7}, {%8,%9}, {%0,%1,%2,%3};"
        : "+f"(c[0]), "+f"(c[1]), "+f"(c[2]), "+f"(c[3])
        : "r"(a[0]), "r"(a[1]), "r"(a[2]), "r"(a[3]), "r"(b[0]), "r"(b[1]));
}

__global__ void __launch_bounds__(256) k_gemm() {
    const int bi = blockIdx.y, bj = blockIdx.x;
    if (bj < bi) return;

    extern __shared__ __align__(16) char smem[];
    const uint32_t sb = smem_to_u32(smem);
    const int tid = threadIdx.x;
    const int wid = tid >> 5, lane = tid & 31;
    const int wm = wid & 1, wn = wid >> 1;     // 2 x 4 warp grid, warp tile 64x32

    if (tid < 128) ((float*)smem)[tid] = g_sq[bj * 128 + tid];

    float acc[4][4][4] = {};

    prefetch_chunk4(bi, bj, 0, sb + OFF_BUF, tid);

#pragma unroll 1
    for (int kb = 0; kb < 8; kb++) {
        if (kb + 1 < 8) {
            prefetch_chunk4(bi, bj, kb + 1, sb + OFF_BUF + ((kb + 1) & 1) * BUF_SZ, tid);
            asm volatile("cp.async.wait_group %0;" :: "n"(1) : "memory");
        } else {
            asm volatile("cp.async.wait_group %0;" :: "n"(0) : "memory");
        }
        __syncthreads();

        const uint32_t sbase = sb + OFF_BUF + (kb & 1) * BUF_SZ;
#pragma unroll
        for (int ks = 0; ks < 4; ks++) {
            uint32_t ah[4][4], al[4][4], bh[4][2], bl[4][2];
#pragma unroll
            for (int mf = 0; mf < 4; mf++) {
                int row = wm * 64 + mf * 16 + (lane & 15);
                int kg = ks * 2 + (lane >> 4);
                uint32_t off = row * 128 + (((unsigned)(kg ^ (row & 7))) << 4);
                asm volatile(
                    "ldmatrix.sync.aligned.m8n8.x4.shared.b16 {%0,%1,%2,%3}, [%4];"
                    : "=r"(ah[mf][0]), "=r"(ah[mf][1]), "=r"(ah[mf][2]), "=r"(ah[mf][3])
                    : "r"(sbase + T_AH + off));
                asm volatile(
                    "ldmatrix.sync.aligned.m8n8.x4.shared.b16 {%0,%1,%2,%3}, [%4];"
                    : "=r"(al[mf][0]), "=r"(al[mf][1]), "=r"(al[mf][2]), "=r"(al[mf][3])
                    : "r"(sbase + T_AL + off));
            }
#pragma unroll
            for (int nf = 0; nf < 4; nf++) {
                int row = wn * 32 + nf * 8 + (lane & 7);
                int kg = ks * 2 + ((lane >> 3) & 1);
                uint32_t off = row * 128 + (((unsigned)(kg ^ (row & 7))) << 4);
                asm volatile(
                    "ldmatrix.sync.aligned.m8n8.x2.shared.b16 {%0,%1}, [%2];"
                    : "=r"(bh[nf][0]), "=r"(bh[nf][1]) : "r"(sbase + T_BH + off));
                asm volatile(
                    "ldmatrix.sync.aligned.m8n8.x2.shared.b16 {%0,%1}, [%2];"
                    : "=r"(bl[nf][0]), "=r"(bl[nf][1]) : "r"(sbase + T_BL + off));
            }
#pragma unroll
            for (int mf = 0; mf < 4; mf++)
#pragma unroll
                for (int nf = 0; nf < 4; nf++) {
                    mma16816(acc[mf][nf], ah[mf], bh[nf]);
                    mma16816(acc[mf][nf], ah[mf], bl[nf]);
                    mma16816(acc[mf][nf], al[mf], bh[nf]);
                }
        }
        __syncthreads();
    }

    // ---------- epilogue: dist -> smem tile -> coalesced (+mirror) stores ----
    const float* s_sqn = (const float*)smem;
    float* Dt = (float*)(smem + OFF_BUF);
    const int gq = lane >> 2, tl = lane & 3;

#pragma unroll
    for (int mf = 0; mf < 4; mf++) {
#pragma unroll
        for (int q = 0; q < 2; q++) {
            int m = wm * 64 + mf * 16 + q * 8 + gq;
            float sqm = g_sq[bi * 128 + m];
#pragma unroll
            for (int nf = 0; nf < 4; nf++) {
                int n = wn * 32 + nf * 8 + tl * 2;
                float v0 = acc[mf][nf][q * 2 + 0];
                float v1 = acc[mf][nf][q * 2 + 1];
                float d0 = sqrtf(fmaxf(sqm + s_sqn[n]     - 2.f * v0, 1e-12f));
                float d1 = sqrtf(fmaxf(sqm + s_sqn[n + 1] - 2.f * v1, 1e-12f));
                Dt[m * 129 + n]     = d0;
                Dt[m * 129 + n + 1] = d1;
            }
        }
    }
    __syncthreads();

#pragma unroll
    for (int k = 0; k < 16; k++) {
        int idx = tid + k * 256;
        int row = idx >> 5, c4 = idx & 31;
        float4 v;
        v.x = Dt[row * 129 + c4 * 4 + 0];
        v.y = Dt[row * 129 + c4 * 4 + 1];
        v.z = Dt[row * 129 + c4 * 4 + 2];
        v.w = Dt[row * 129 + c4 * 4 + 3];
        *(float4*)&g_dist[(size_t)(bi * 128 + row) * NROW + bj * 128 + c4 * 4] = v;
    }
    if (bi != bj) {
#pragma unroll
        for (int k = 0; k < 16; k++) {
            int idx = tid + k * 256;
            int mrow = idx >> 5, c4 = idx & 31;
            float4 v;
            v.x = Dt[(c4 * 4 + 0) * 129 + mrow];
            v.y = Dt[(c4 * 4 + 1) * 129 + mrow];
            v.z = Dt[(c4 * 4 + 2) * 129 + mrow];
            v.w = Dt[(c4 * 4 + 3) * 129 + mrow];
            *(float4*)&g_dist[(size_t)(bj * 128 + mrow) * NROW + bi * 128 + c4 * 4] = v;
        }
    }
}

// ---------------- block-wide u64 max reduce, 512 thr (broadcast) ----------------
__device__ unsigned long long blockMax64(unsigned long long v,
                                         volatile unsigned long long* sh, int tid) {
#pragma unroll
    for (int o = 16; o > 0; o >>= 1) {
        unsigned long long o2 = __shfl_xor_sync(0xffffffffu, v, o);
        if (o2 > v) v = o2;
    }
    if ((tid & 31) == 0) sh[tid >> 5] = v;
    __syncthreads();
    if (tid == 0) {
        unsigned long long m = sh[0];
#pragma unroll
        for (int w = 1; w < 16; w++) { unsigned long long x = sh[w]; if (x > m) m = x; }
        sh[16] = m;
    }
    __syncthreads();
    return sh[16];
}

// ---------------- k_row: per-row reduce (512 threads) ----------------
__global__ void __launch_bounds__(512) k_row(
    const float* __restrict__ pred, const int* __restrict__ targets,
    const float* __restrict__ prob, const float* __restrict__ thrp,
    unsigned kp0, unsigned kp1, unsigned q0, unsigned q1)
{
    const int i = blockIdx.x;
    const int tid = threadIdx.x;
    const float thr = *thrp;
    const int ti = targets[i];
    const float* grow = g_dist + (size_t)i * NROW;
    const float INF = devInf();

    __shared__ unsigned long long sh[17];

    float lv[8];
    unsigned long long g1 = 0, g2 = 0, cand = 0;
    const unsigned mrow = (unsigned)i * (unsigned)NROW;
#pragma unroll
    for (int w = 0; w < 8; w++) {
        int j = tid + w * 512;
        float d = grow[j];
        bool same = (targets[j] == ti);
        float v = same ? INF : d;
        lv[w] = v;
        unsigned fb = __float_as_uint(v);
        unsigned long long sc = ~(((unsigned long long)fb << 13) | (unsigned)j);
        if (sc > cand) cand = sc;
        if (same && j != i) {
            unsigned m = mrow + (unsigned)j;
            unsigned b1 = rbits32(kp0, kp1, m);
            unsigned long long s1 = (1ULL << 62) |
                ((unsigned long long)(b1 >> 9) << 13) | (unsigned)(NROW - 1 - j);
            if (s1 > g1) g1 = s1;
            if (prob[j] >= thr) {
                unsigned b2 = rbits32(q0, q1, m);
                unsigned long long s2 = (1ULL << 62) |
                    ((unsigned long long)(b2 >> 9) << 13) | (unsigned)(NROW - 1 - j);
                if (s2 > g2) g2 = s2;
            }
        }
    }

    unsigned long long r1 = blockMax64(g1, sh, tid);
    unsigned long long r2 = blockMax64(g2, sh, tid);
    int ap_idx  = r1 ? (NROW - 1 - (int)(r1 & 0x1FFFu)) : 0;
    int new_pos = r2 ? (NROW - 1 - (int)(r2 & 0x1FFFu)) : ap_idx;

    int st[KTOP];
#pragma unroll
    for (int t = 0; t < KTOP; t++) {
        unsigned long long r = blockMax64(cand, sh, tid);
        int sel = (int)((~r) & 0x1FFFu);
        st[t] = sel;
        if ((sel & 511) == tid) {
            lv[sel >> 9] = INF;
            unsigned long long c2 = 0;
#pragma unroll
            for (int w = 0; w < 8; w++) {
                unsigned fb = __float_as_uint(lv[w]);
                unsigned long long sc = ~(((unsigned long long)fb << 13) |
                                          (unsigned)(tid + w * 512));
                if (sc > c2) c2 = sc;
            }
            cand = c2;
        }
    }
    int an_idx = st[0];

    unsigned long long pm = 0;
    if (tid < NCLS) {
        float v = pred[(size_t)an_idx * NCLS + tid];
        unsigned b = __float_as_uint(v);
        unsigned ord = (b & 0x80000000u) ? ~b : (b | 0x80000000u);
        pm = ((unsigned long long)ord << 13) | (unsigned)(NCLS - 1 - tid);
    }
    unsigned long long rp = blockMax64(pm, sh, tid);
    int pargmax = NCLS - 1 - (int)(rp & 0x1FFFu);

    if (tid == 0) {
        float ap0 = grow[ap_idx];
        float an0 = grow[an_idx];
        bool pos_conf = prob[ap_idx] >= thr;
        bool neg_conf = prob[an_idx] >= thr;
        bool is_fn = (pargmax == ti);

        int rsel = KTOP - 1;
#pragma unroll
        for (int t = KTOP - 2; t >= 1; t--) {
            if (prob[st[t]] >= thr) rsel = t;
        }
        float an_B   = grow[st[rsel]];
        float ap_new = grow[new_pos];

        bool caseB   = pos_conf && !neg_conf && is_fn;
        bool swapc   = !pos_conf && (neg_conf || !is_fn);
        bool inverse = !pos_conf && !neg_conf && is_fn;
        float half = (ap0 + an0) * 0.5f;
        float ap = caseB ? half : (swapc ? ap_new : ap0);
        float an = caseB ? an_B : (swapc ? half  : an0);
        float rl = inverse ? fmaxf(an - ap + 0.3f, 0.f)
                           : fmaxf(ap - an + 0.3f, 0.f);
        bool conf = prob[i] >= thr;
        g_rowloss[i] = conf ? rl : 0.f;
        g_flags[i] = (conf ? 1 : 0) | ((conf && an >= ap) ? 2 : 0);
    }
}

// ---------------- k_final: deterministic final reduce ----------------
__global__ void __launch_bounds__(256) k_final(float* out) {
    __shared__ float ss[256];
    __shared__ int sc[256], sk[256];
    int tid = threadIdx.x;
    float s = 0.f; int c = 0, k = 0;
    for (int r = tid; r < NROW; r += 256) {
        s += g_rowloss[r];
        int f = g_flags[r];
        c += f & 1;
        k += (f >> 1) & 1;
    }
    ss[tid] = s; sc[tid] = c; sk[tid] = k;
    __syncthreads();
    for (int o = 128; o > 0; o >>= 1) {
        if (tid < o) { ss[tid] += ss[tid + o]; sc[tid] += sc[tid + o]; sk[tid] += sk[tid + o]; }
        __syncthreads();
    }
    if (tid == 0) {
        int cnt = sc[0]; if (cnt < 1) cnt = 1;
        out[0] = ss[0] / (float)cnt;
        out[1] = (float)sk[0];
    }
}

}  // namespace

extern "C" void kernel_launch(void* const* d_in, const int* in_sizes, int n_in,
                              void* d_out, int out_size) {
    const float* X       = (const float*)d_in[0];
    const float* pred    = (const float*)d_in[1];
    const int*   targets = (const int*)d_in[2];
    // d_in[3] = true_targets (unused by reference)
    const float* prob    = (const float*)d_in[4];
    const float* thr     = (const float*)d_in[5];
    float* out = (float*)d_out;

    cudaFuncSetAttribute(k_gemm, cudaFuncAttributeMaxDynamicSharedMemorySize,
                         SMEM_DYN);

    // JAX partitionable split: child key i = threefry2x32((0,42), (0, i))
    uint2 kp  = tf2x32(0u, 42u, 0u, 0u);
    uint2 kp2 = tf2x32(0u, 42u, 0u, 1u);

    k_prep<<<NROW / 8, 256>>>(X);
    dim3 g(NROW / 128, NROW / 128);
    k_gemm<<<g, 256, SMEM_DYN>>>();
    k_row<<<NROW, 512>>>(pred, targets, prob, thr, kp.x, kp.y, kp2.x, kp2.y);
    k_final<<<1, 256>>>(out);
}

// round 8
// speedup vs baseline: 1.0410x; 1.0410x over previous
#include <cuda_runtime.h>
#include <cuda_bf16.h>
#include <cstdint>

// RobustTripletLoss — N=4096, D=512, C=128, TOPK=12
// k_prep : X fp32 -> (Xhi, Xlo) bf16 split + row sq-norms
// k_gemm : HMMA (mma.sync bf16) symmetric Gram, 3-term hi/lo split, cp.async
//          double-buffered (R6 proven config) -> dist (64MB scratch)
// k_row  : per-row reduce (top-12, threefry gumbel, case logic) + last-CTA
//          deterministic final reduction -> out[0]=loss, out[1]=(float)correct

namespace {

constexpr int NROW = 4096;
constexpr int DIM  = 512;
constexpr int NCLS = 128;
constexpr int KTOP = 12;

__device__ __align__(16) float g_dist[(size_t)NROW * NROW];
__device__ __align__(16) float g_sq[NROW];
__device__ __align__(16) __nv_bfloat16 g_xhi[(size_t)NROW * DIM];
__device__ __align__(16) __nv_bfloat16 g_xlo[(size_t)NROW * DIM];
__device__ float g_rowloss[NROW];
__device__ int   g_flags[NROW];
__device__ int   g_ctr = 0;

// ---------------- threefry2x32-20 (exact JAX semantics) ----------------
__host__ __device__ inline uint2 tf2x32(unsigned k0, unsigned k1,
                                        unsigned x0, unsigned x1) {
    unsigned ks2 = k0 ^ k1 ^ 0x1BD11BDAu;
    x0 += k0; x1 += k1;
#define TF_R(r) { x0 += x1; x1 = (x1 << (r)) | (x1 >> (32 - (r))); x1 ^= x0; }
    TF_R(13) TF_R(15) TF_R(26) TF_R(6)
    x0 += k1;  x1 += ks2 + 1u;
    TF_R(17) TF_R(29) TF_R(16) TF_R(24)
    x0 += ks2; x1 += k0 + 2u;
    TF_R(13) TF_R(15) TF_R(26) TF_R(6)
    x0 += k0;  x1 += k1 + 3u;
    TF_R(17) TF_R(29) TF_R(16) TF_R(24)
    x0 += k1;  x1 += ks2 + 4u;
    TF_R(13) TF_R(15) TF_R(26) TF_R(6)
    x0 += ks2; x1 += k0 + 5u;
#undef TF_R
    uint2 r; r.x = x0; r.y = x1; return r;
}

__device__ __forceinline__ unsigned rbits32(unsigned k0, unsigned k1, unsigned m) {
    uint2 e = tf2x32(k0, k1, 0u, m);
    return e.x ^ e.y;
}

__device__ __forceinline__ float devInf() { return __int_as_float(0x7f800000); }

__device__ __forceinline__ uint32_t smem_to_u32(const void* p) {
    uint32_t a;
    asm("{ .reg .u64 t; cvta.to.shared.u64 t, %1; cvt.u32.u64 %0, t; }"
        : "=r"(a) : "l"(p));
    return a;
}

// ---------------- k_prep: bf16 hi/lo split + row norms ----------------
__global__ void __launch_bounds__(256) k_prep(const float* __restrict__ X) {
    int row  = blockIdx.x * 8 + (threadIdx.x >> 5);
    int lane = threadIdx.x & 31;
    const float4* p = (const float4*)(X + (size_t)row * DIM);
    float s = 0.f;
#pragma unroll
    for (int it = 0; it < 4; it++) {
        int f = lane + it * 32;
        float4 v = p[f];
        s = fmaf(v.x, v.x, fmaf(v.y, v.y, fmaf(v.z, v.z, fmaf(v.w, v.w, s))));
        __nv_bfloat16 h0 = __float2bfloat16(v.x);
        __nv_bfloat16 h1 = __float2bfloat16(v.y);
        __nv_bfloat16 h2 = __float2bfloat16(v.z);
        __nv_bfloat16 h3 = __float2bfloat16(v.w);
        __nv_bfloat16 l0 = __float2bfloat16(v.x - __bfloat162float(h0));
        __nv_bfloat16 l1 = __float2bfloat16(v.y - __bfloat162float(h1));
        __nv_bfloat16 l2 = __float2bfloat16(v.z - __bfloat162float(h2));
        __nv_bfloat16 l3 = __float2bfloat16(v.w - __bfloat162float(h3));
        size_t base = (size_t)row * DIM + (size_t)f * 4;
        *(__nv_bfloat162*)&g_xhi[base]     = __halves2bfloat162(h0, h1);
        *(__nv_bfloat162*)&g_xhi[base + 2] = __halves2bfloat162(h2, h3);
        *(__nv_bfloat162*)&g_xlo[base]     = __halves2bfloat162(l0, l1);
        *(__nv_bfloat162*)&g_xlo[base + 2] = __halves2bfloat162(l2, l3);
    }
#pragma unroll
    for (int o = 16; o > 0; o >>= 1) s += __shfl_xor_sync(0xffffffffu, s, o);
    if (lane == 0) g_sq[row] = s;
}

// ---------------- k_gemm: HMMA bf16x3 symmetric Gram (R6 config) ----------------
// smem: [0..512) sqn stage | [512..) two 32KB buffers (A 16K + B 16K each)
// Dt (float 128x129) reuses [512..66560) after compute.
constexpr int OFF_BUF  = 512;
constexpr int BUF_SZ   = 32768;
constexpr int SMEM_DYN = 512 + 128 * 129 * 4;  // 66560

__device__ __forceinline__ void prefetch_chunk(
    const __nv_bfloat16* __restrict__ srcA, const __nv_bfloat16* __restrict__ srcB,
    int bi, int bj, int kb, uint32_t sbuf, int tid)
{
#pragma unroll
    for (int it = 0; it < 4; it++) {
        int idx = tid + it * 256;
        int row = idx >> 3, g = idx & 7;
        unsigned sw = ((unsigned)(g ^ (row & 7))) << 4;
        const void* gA = srcA + (size_t)(bi * 128 + row) * DIM + kb * 64 + g * 8;
        uint32_t dA = sbuf + row * 128 + sw;
        asm volatile("cp.async.cg.shared.global [%0], [%1], 16;" :: "r"(dA), "l"(gA));
        const void* gB = srcB + (size_t)(bj * 128 + row) * DIM + kb * 64 + g * 8;
        uint32_t dB = sbuf + 16384 + row * 128 + sw;
        asm volatile("cp.async.cg.shared.global [%0], [%1], 16;" :: "r"(dB), "l"(gB));
    }
    asm volatile("cp.async.commit_group;" ::: "memory");
}

__device__ __forceinline__ void mma16816(float* c, const uint32_t* a,
                                         const uint32_t* b) {
    asm volatile(
        "mma.sync.aligned.m16n8k16.row.col.f32.bf16.bf16.f32 "
        "{%0,%1,%2,%3}, {%4,%5,%6,%7}, {%8,%9}, {%0,%1,%2,%3};"
        : "+f"(c[0]), "+f"(c[1]), "+f"(c[2]), "+f"(c[3])
        : "r"(a[0]), "r"(a[1]), "r"(a[2]), "r"(a[3]), "r"(b[0]), "r"(b[1]));
}

__global__ void __launch_bounds__(256) k_gemm() {
    const int bi = blockIdx.y, bj = blockIdx.x;
    if (bj < bi) return;

    extern __shared__ __align__(16) char smem[];
    const uint32_t sb = smem_to_u32(smem);
    const int tid = threadIdx.x;
    const int wid = tid >> 5, lane = tid & 31;
    const int wm = wid & 1, wn = wid >> 1;     // 2 x 4 warp grid, warp tile 64x32

    if (tid < 128) ((float*)smem)[tid] = g_sq[bj * 128 + tid];

    float acc[4][4][4] = {};

    // chunk c (0..23): term t = c>>3 in {(hi,hi),(hi,lo),(lo,hi)}, kb = c&7
    prefetch_chunk(g_xhi, g_xhi, bi, bj, 0, sb + OFF_BUF, tid);

#pragma unroll 1
    for (int c = 0; c < 24; c++) {
        if (c + 1 < 24) {
            int t = (c + 1) >> 3, kb = (c + 1) & 7;
            const __nv_bfloat16* sA = (t < 2) ? g_xhi : g_xlo;
            const __nv_bfloat16* sB = (t == 1) ? g_xlo : g_xhi;
            prefetch_chunk(sA, sB, bi, bj, kb, sb + OFF_BUF + ((c + 1) & 1) * BUF_SZ, tid);
            asm volatile("cp.async.wait_group %0;" :: "n"(1) : "memory");
        } else {
            asm volatile("cp.async.wait_group %0;" :: "n"(0) : "memory");
        }
        __syncthreads();

        const uint32_t sA = sb + OFF_BUF + (c & 1) * BUF_SZ;
        const uint32_t sB = sA + 16384;
#pragma unroll
        for (int ks = 0; ks < 4; ks++) {
            uint32_t a[4][4], b[4][2];
#pragma unroll
            for (int mf = 0; mf < 4; mf++) {
                int row = wm * 64 + mf * 16 + (lane & 15);
                int kg = ks * 2 + (lane >> 4);
                uint32_t addr = sA + row * 128 + (((unsigned)(kg ^ (row & 7))) << 4);
                asm volatile(
                    "ldmatrix.sync.aligned.m8n8.x4.shared.b16 {%0,%1,%2,%3}, [%4];"
                    : "=r"(a[mf][0]), "=r"(a[mf][1]), "=r"(a[mf][2]), "=r"(a[mf][3])
                    : "r"(addr));
            }
#pragma unroll
            for (int nf = 0; nf < 4; nf++) {
                int row = wn * 32 + nf * 8 + (lane & 7);
                int kg = ks * 2 + ((lane >> 3) & 1);
                uint32_t addr = sB + row * 128 + (((unsigned)(kg ^ (row & 7))) << 4);
                asm volatile(
                    "ldmatrix.sync.aligned.m8n8.x2.shared.b16 {%0,%1}, [%2];"
                    : "=r"(b[nf][0]), "=r"(b[nf][1]) : "r"(addr));
            }
#pragma unroll
            for (int mf = 0; mf < 4; mf++)
#pragma unroll
                for (int nf = 0; nf < 4; nf++)
                    mma16816(acc[mf][nf], a[mf], b[nf]);
        }
        __syncthreads();
    }

    // ---------- epilogue: dist -> smem tile -> coalesced (+mirror) stores ----
    const float* s_sqn = (const float*)smem;
    float* Dt = (float*)(smem + OFF_BUF);
    const int gq = lane >> 2, tl = lane & 3;

#pragma unroll
    for (int mf = 0; mf < 4; mf++) {
#pragma unroll
        for (int q = 0; q < 2; q++) {
            int m = wm * 64 + mf * 16 + q * 8 + gq;
            float sqm = g_sq[bi * 128 + m];
#pragma unroll
            for (int nf = 0; nf < 4; nf++) {
                int n = wn * 32 + nf * 8 + tl * 2;
                float v0 = acc[mf][nf][q * 2 + 0];
                float v1 = acc[mf][nf][q * 2 + 1];
                float d0 = sqrtf(fmaxf(sqm + s_sqn[n]     - 2.f * v0, 1e-12f));
                float d1 = sqrtf(fmaxf(sqm + s_sqn[n + 1] - 2.f * v1, 1e-12f));
                Dt[m * 129 + n]     = d0;
                Dt[m * 129 + n + 1] = d1;
            }
        }
    }
    __syncthreads();

#pragma unroll
    for (int k = 0; k < 16; k++) {
        int idx = tid + k * 256;
        int row = idx >> 5, c4 = idx & 31;
        float4 v;
        v.x = Dt[row * 129 + c4 * 4 + 0];
        v.y = Dt[row * 129 + c4 * 4 + 1];
        v.z = Dt[row * 129 + c4 * 4 + 2];
        v.w = Dt[row * 129 + c4 * 4 + 3];
        *(float4*)&g_dist[(size_t)(bi * 128 + row) * NROW + bj * 128 + c4 * 4] = v;
    }
    if (bi != bj) {
#pragma unroll
        for (int k = 0; k < 16; k++) {
            int idx = tid + k * 256;
            int mrow = idx >> 5, c4 = idx & 31;
            float4 v;
            v.x = Dt[(c4 * 4 + 0) * 129 + mrow];
            v.y = Dt[(c4 * 4 + 1) * 129 + mrow];
            v.z = Dt[(c4 * 4 + 2) * 129 + mrow];
            v.w = Dt[(c4 * 4 + 3) * 129 + mrow];
            *(float4*)&g_dist[(size_t)(bj * 128 + mrow) * NROW + bi * 128 + c4 * 4] = v;
        }
    }
}

// ---------------- block-wide u64 max reduce (broadcast result) ----------------
__device__ unsigned long long blockMax64(unsigned long long v,
                                         volatile unsigned long long* sh, int tid) {
#pragma unroll
    for (int o = 16; o > 0; o >>= 1) {
        unsigned long long o2 = __shfl_xor_sync(0xffffffffu, v, o);
        if (o2 > v) v = o2;
    }
    if ((tid & 31) == 0) sh[tid >> 5] = v;
    __syncthreads();
    if (tid == 0) {
        unsigned long long m = sh[0];
#pragma unroll
        for (int w = 1; w < 8; w++) { unsigned long long x = sh[w]; if (x > m) m = x; }
        sh[8] = m;
    }
    __syncthreads();
    return sh[8];
}

// ---------------- k_row: per-row reduce + last-CTA final reduce ----------------
__global__ void __launch_bounds__(256) k_row(
    const float* __restrict__ pred, const int* __restrict__ targets,
    const float* __restrict__ prob, const float* __restrict__ thrp,
    unsigned kp0, unsigned kp1, unsigned q0, unsigned q1, float* out)
{
    const int i = blockIdx.x;
    const int tid = threadIdx.x;
    const float thr = *thrp;
    const int ti = targets[i];
    const float* grow = g_dist + (size_t)i * NROW;
    const float INF = devInf();

    __shared__ unsigned long long sh[9];
    __shared__ int slast;

    float lv[16];
    unsigned long long g1 = 0, g2 = 0, cand = 0;
    const unsigned mrow = (unsigned)i * (unsigned)NROW;
#pragma unroll
    for (int w = 0; w < 16; w++) {
        int j = tid + w * 256;
        float d = grow[j];
        bool same = (targets[j] == ti);
        float v = same ? INF : d;
        lv[w] = v;
        unsigned fb = __float_as_uint(v);
        unsigned long long sc = ~(((unsigned long long)fb << 13) | (unsigned)j);
        if (sc > cand) cand = sc;
        if (same && j != i) {
            unsigned m = mrow + (unsigned)j;
            unsigned b1 = rbits32(kp0, kp1, m);
            unsigned long long s1 = (1ULL << 62) |
                ((unsigned long long)(b1 >> 9) << 13) | (unsigned)(NROW - 1 - j);
            if (s1 > g1) g1 = s1;
            if (prob[j] >= thr) {
                unsigned b2 = rbits32(q0, q1, m);
                unsigned long long s2 = (1ULL << 62) |
                    ((unsigned long long)(b2 >> 9) << 13) | (unsigned)(NROW - 1 - j);
                if (s2 > g2) g2 = s2;
            }
        }
    }

    unsigned long long r1 = blockMax64(g1, sh, tid);
    unsigned long long r2 = blockMax64(g2, sh, tid);
    int ap_idx  = r1 ? (NROW - 1 - (int)(r1 & 0x1FFFu)) : 0;
    int new_pos = r2 ? (NROW - 1 - (int)(r2 & 0x1FFFu)) : ap_idx;

    int st[KTOP];
#pragma unroll
    for (int t = 0; t < KTOP; t++) {
        unsigned long long r = blockMax64(cand, sh, tid);
        int sel = (int)((~r) & 0x1FFFu);
        st[t] = sel;
        if ((sel & 255) == tid) {
            lv[sel >> 8] = INF;
            unsigned long long c2 = 0;
#pragma unroll
            for (int w = 0; w < 16; w++) {
                unsigned fb = __float_as_uint(lv[w]);
                unsigned long long sc = ~(((unsigned long long)fb << 13) |
                                          (unsigned)(tid + w * 256));
                if (sc > c2) c2 = sc;
            }
            cand = c2;
        }
    }
    int an_idx = st[0];

    unsigned long long pm = 0;
    if (tid < NCLS) {
        float v = pred[(size_t)an_idx * NCLS + tid];
        unsigned b = __float_as_uint(v);
        unsigned ord = (b & 0x80000000u) ? ~b : (b | 0x80000000u);
        pm = ((unsigned long long)ord << 13) | (unsigned)(NCLS - 1 - tid);
    }
    unsigned long long rp = blockMax64(pm, sh, tid);
    int pargmax = NCLS - 1 - (int)(rp & 0x1FFFu);

    if (tid == 0) {
        float ap0 = grow[ap_idx];
        float an0 = grow[an_idx];
        bool pos_conf = prob[ap_idx] >= thr;
        bool neg_conf = prob[an_idx] >= thr;
        bool is_fn = (pargmax == ti);

        int rsel = KTOP - 1;
#pragma unroll
        for (int t = KTOP - 2; t >= 1; t--) {
            if (prob[st[t]] >= thr) rsel = t;
        }
        float an_B   = grow[st[rsel]];
        float ap_new = grow[new_pos];

        bool caseB   = pos_conf && !neg_conf && is_fn;
        bool swapc   = !pos_conf && (neg_conf || !is_fn);
        bool inverse = !pos_conf && !neg_conf && is_fn;
        float half = (ap0 + an0) * 0.5f;
        float ap = caseB ? half : (swapc ? ap_new : ap0);
        float an = caseB ? an_B : (swapc ? half  : an0);
        float rl = inverse ? fmaxf(an - ap + 0.3f, 0.f)
                           : fmaxf(ap - an + 0.3f, 0.f);
        bool conf = prob[i] >= thr;
        g_rowloss[i] = conf ? rl : 0.f;
        g_flags[i] = (conf ? 1 : 0) | ((conf && an >= ap) ? 2 : 0);
        __threadfence();
        int old = atomicAdd(&g_ctr, 1);
        slast = (old == NROW - 1) ? 1 : 0;
    }
    __syncthreads();

    // last CTA: deterministic final reduction (fixed read order)
    if (slast) {
        __threadfence();
        __shared__ float ss[256];
        __shared__ int scn[256], skk[256];
        float s = 0.f; int c = 0, k = 0;
        for (int r = tid; r < NROW; r += 256) {
            s += g_rowloss[r];
            int f = g_flags[r];
            c += f & 1;
            k += (f >> 1) & 1;
        }
        ss[tid] = s; scn[tid] = c; skk[tid] = k;
        __syncthreads();
        for (int o = 128; o > 0; o >>= 1) {
            if (tid < o) { ss[tid] += ss[tid + o]; scn[tid] += scn[tid + o]; skk[tid] += skk[tid + o]; }
            __syncthreads();
        }
        if (tid == 0) {
            int cnt = scn[0]; if (cnt < 1) cnt = 1;
            out[0] = ss[0] / (float)cnt;
            out[1] = (float)skk[0];
            g_ctr = 0;   // reset for next graph replay
        }
    }
}

}  // namespace

extern "C" void kernel_launch(void* const* d_in, const int* in_sizes, int n_in,
                              void* d_out, int out_size) {
    const float* X       = (const float*)d_in[0];
    const float* pred    = (const float*)d_in[1];
    const int*   targets = (const int*)d_in[2];
    // d_in[3] = true_targets (unused by reference)
    const float* prob    = (const float*)d_in[4];
    const float* thr     = (const float*)d_in[5];
    float* out = (float*)d_out;

    cudaFuncSetAttribute(k_gemm, cudaFuncAttributeMaxDynamicSharedMemorySize,
                         SMEM_DYN);

    // JAX partitionable split: child key i = threefry2x32((0,42), (0, i))
    uint2 kp  = tf2x32(0u, 42u, 0u, 0u);
    uint2 kp2 = tf2x32(0u, 42u, 0u, 1u);

    k_prep<<<NROW / 8, 256>>>(X);
    dim3 g(NROW / 128, NROW / 128);
    k_gemm<<<g, 256, SMEM_DYN>>>();
    k_row<<<NROW, 256>>>(pred, targets, prob, thr, kp.x, kp.y, kp2.x, kp2.y, out);
}